// round 11
// baseline (speedup 1.0000x reference)
#include <cuda_runtime.h>
#include <cuda_bf16.h>
#include <cstdint>

// ---------------------------------------------------------------------------
// LoRA multi-task MLP via mma.sync bf16 (plain sm_100 target).
// fp32 split hi/lo bf16 stored [hi|lo] (2K wide). Single K-pass GEMM, 3 MMA
// terms per chunk: acc = Ahi*Bhi + Ahi*Blo + Alo*Bhi (fp32 accumulate).
// Round 11: 4-warp CTA (128 thr), warp tile 64x64, BM=BN=128, 3 stages.
// Square warp tile cuts smem crossbar traffic 256->192 KB/chunk (the R6
// binding constraint) while keeping R6's proven grid/stage geometry.
// ---------------------------------------------------------------------------

#define T_TASKS 8
#define RNK 8
#define M_ROWS 8192

#define BM 128
#define BN 128
#define BK 64                         // true-K elements per chunk (128 B rows)
#define STAGES 3
#define NTHR 128
#define TILE_BYTES (128 * 128)        // 16 KB per operand tile
#define STAGE_BYTES (4 * TILE_BYTES)  // Ahi|Alo|Bhi|Blo = 64 KB
#define SMEM_BYTES (STAGES * STAGE_BYTES)   // 192 KB

// ---- scratch (device globals; no allocation allowed) ----------------------
__device__ __nv_bfloat16 g_A0[(size_t)M_ROWS * 4096];   // [hi|lo], 64 MB
__device__ __nv_bfloat16 g_A1[(size_t)M_ROWS * 4096];   // [hi|lo], 64 MB
__device__ __nv_bfloat16 g_B [(size_t)2048   * 4096];   // [hi|lo], 16 MB
__device__ float g_p [M_ROWS * RNK];
__device__ float g_pp[16 * M_ROWS * RNK];               // per-n-block partials

// ---------------------------------------------------------------------------
__device__ __forceinline__ uint32_t smem_u32(const void* p) {
    uint32_t a;
    asm("{ .reg .u64 t; cvta.to.shared.u64 t, %1; cvt.u32.u64 %0, t; }"
        : "=r"(a) : "l"(p));
    return a;
}

#define CP_ASYNC16(smem, gptr) \
    asm volatile("cp.async.cg.shared.global [%0], [%1], 16;" \
                 :: "r"(smem), "l"(gptr) : "memory")
#define CP_ASYNC_COMMIT() asm volatile("cp.async.commit_group;" ::: "memory")
#define CP_ASYNC_WAIT(n)  asm volatile("cp.async.wait_group %0;" :: "n"(n) : "memory")

#define LDMATRIX_X4(r0,r1,r2,r3,addr) \
    asm volatile("ldmatrix.sync.aligned.m8n8.x4.shared.b16 {%0,%1,%2,%3}, [%4];" \
        : "=r"(r0),"=r"(r1),"=r"(r2),"=r"(r3) : "r"(addr))

__device__ __forceinline__ void mma_bf16(float* c, const uint32_t* a,
                                         const uint32_t* b) {
    asm volatile(
        "mma.sync.aligned.m16n8k16.row.col.f32.bf16.bf16.f32 "
        "{%0,%1,%2,%3}, {%4,%5,%6,%7}, {%8,%9}, {%0,%1,%2,%3};"
        : "+f"(c[0]), "+f"(c[1]), "+f"(c[2]), "+f"(c[3])
        : "r"(a[0]), "r"(a[1]), "r"(a[2]), "r"(a[3]), "r"(b[0]), "r"(b[1]));
}

// ---------------------------------------------------------------------------
// Fused layer-0 prep: x fp32 -> A0 bf16 [hi|lo] AND P0[m,r] = x·D0[:,r,t].
// ---------------------------------------------------------------------------
__global__ __launch_bounds__(256)
void prep0_kernel(const float* __restrict__ x, const float* __restrict__ D,
                  __nv_bfloat16* __restrict__ Ap, float* __restrict__ P)
{
    __shared__ float Ds[RNK][1024];
    const int tid  = threadIdx.x;
    const int wid  = tid >> 5;
    const int lane = tid & 31;
    const int row  = blockIdx.x * 8 + wid;
    const int t    = (blockIdx.x * 8) >> 10;

    for (int idx = tid; idx < 1024 * RNK; idx += 256) {
        int k = idx >> 3, r = idx & 7;
        Ds[r][k] = D[(size_t)k * 64 + r * 8 + t];
    }
    __syncthreads();

    const float4* xr = reinterpret_cast<const float4*>(x + (size_t)row * 1024);
    __nv_bfloat16* arow = Ap + (size_t)row * 2048;
    float acc[RNK];
#pragma unroll
    for (int r = 0; r < RNK; ++r) acc[r] = 0.f;
#pragma unroll
    for (int i = 0; i < 8; ++i) {
        int kq = lane + 32 * i;
        float4 v = xr[kq];
        int k = kq << 2;
        union { __nv_bfloat16 b[4]; uint2 u; } hp, lp;
        float vv[4] = {v.x, v.y, v.z, v.w};
#pragma unroll
        for (int j = 0; j < 4; ++j) {
            __nv_bfloat16 h = __float2bfloat16(vv[j]);
            hp.b[j] = h;
            lp.b[j] = __float2bfloat16(vv[j] - __bfloat162float(h));
        }
        *reinterpret_cast<uint2*>(arow + k)        = hp.u;
        *reinterpret_cast<uint2*>(arow + 1024 + k) = lp.u;
#pragma unroll
        for (int r = 0; r < RNK; ++r) {
            float4 d = *reinterpret_cast<const float4*>(&Ds[r][k]);
            acc[r] += v.x * d.x + v.y * d.y + v.z * d.z + v.w * d.w;
        }
    }
#pragma unroll
    for (int r = 0; r < RNK; ++r) {
        float v = acc[r];
#pragma unroll
        for (int o = 16; o > 0; o >>= 1) v += __shfl_down_sync(0xffffffffu, v, o);
        if (lane == 0) P[(size_t)row * RNK + r] = v;
    }
}

// ---------------------------------------------------------------------------
// P[m,r] = sum_nb Pp[nb][m][r]
// ---------------------------------------------------------------------------
__global__ __launch_bounds__(256)
void reduceP_kernel(const float* __restrict__ Pp, float* __restrict__ P, int nb)
{
    int i = blockIdx.x * 256 + threadIdx.x;      // over M_ROWS*RNK = 65536
    float s = 0.f;
    for (int b = 0; b < nb; ++b) s += Pp[(size_t)b * (M_ROWS * RNK) + i];
    P[i] = s;
}

// ---------------------------------------------------------------------------
// W[K,N] fp32 -> B'[N,2K] bf16 = [hi^T | lo^T]
// ---------------------------------------------------------------------------
__global__ __launch_bounds__(256)
void convertW_kernel(const float* __restrict__ W, __nv_bfloat16* __restrict__ Bp,
                     int K, int N)
{
    __shared__ float t[32][33];
    int n0 = blockIdx.x * 32, k0 = blockIdx.y * 32;
    int tx = threadIdx.x & 31, ty = threadIdx.x >> 5;   // 32 x 8
#pragma unroll
    for (int i = 0; i < 4; ++i)
        t[ty + 8 * i][tx] = W[(size_t)(k0 + ty + 8 * i) * N + n0 + tx];
    __syncthreads();
#pragma unroll
    for (int i = 0; i < 4; ++i) {
        int nn = ty + 8 * i;
        float v = t[tx][nn];
        __nv_bfloat16 h = __float2bfloat16(v);
        __nv_bfloat16 l = __float2bfloat16(v - __bfloat162float(h));
        size_t rb = (size_t)(n0 + nn) * 2 * K + k0 + tx;
        Bp[rb]     = h;
        Bp[rb + K] = l;
    }
}

// ---------------------------------------------------------------------------
// 3-stage pipelined bf16 mma.sync GEMM, 4 warps (2m x 2n), warp tile 64x64,
// 3 terms per chunk, paired ldmatrix.x4 for B, fused epilogue + race-free
// next-layer LoRA partials.
// mode==1: bf16 [hi|lo] output (stride 2N) + ReLU + fused P partials (Dn).
// mode==0: fp32 output (stride N), no ReLU, no P partials.
// ---------------------------------------------------------------------------
__global__ __launch_bounds__(NTHR, 1)
void gemm_mma_kernel(const __nv_bfloat16* __restrict__ Ap,
                     const __nv_bfloat16* __restrict__ Bp,
                     const float* __restrict__ bias,
                     const float* __restrict__ P,
                     const float* __restrict__ U,
                     void* __restrict__ Cp,
                     const float* __restrict__ Dn,   // next-layer D or null
                     float* __restrict__ Pp,         // partial buffer or null
                     int K, int N, int mode)
{
    extern __shared__ char smem[];
    const uint32_t sbase = smem_u32(smem);
    const int tid  = threadIdx.x;
    const int wid  = tid >> 5;
    const int lane = tid & 31;
    const int mBase = blockIdx.y * BM;
    const int nBase = blockIdx.x * BN;
    const int task  = mBase >> 10;
    const uint32_t ld = 2 * (uint32_t)K;
    const int nChunks = K / BK;

    const int warp_m = (wid >> 1) * 64;   // 0 / 64
    const int warp_n = (wid & 1) * 64;    // 0 / 64

    // ---- producer addressing: 8 granules per tile per thread ---------------
    uint32_t sAB[8], oA[8], oB[8];
#pragma unroll
    for (int i = 0; i < 8; ++i) {
        int g = tid + (i << 7);           // 16B granule id 0..1023
        int r = g >> 3, q = g & 7;        // row 0..127, 16B col 0..7
        uint32_t off = (uint32_t)(r << 7) + (q << 4);
        sAB[i] = off ^ ((uint32_t)(r & 7) << 4);
        oA[i] = (uint32_t)(mBase + r) * ld + (q << 3);
        oB[i] = (uint32_t)(nBase + r) * ld + (q << 3);
    }

    float acc[4][8][4];
#pragma unroll
    for (int mi = 0; mi < 4; ++mi)
#pragma unroll
        for (int ni = 0; ni < 8; ++ni)
#pragma unroll
            for (int j = 0; j < 4; ++j) acc[mi][ni][j] = 0.f;

    // ---- prologue: fill STAGES-1 stages -----------------------------------
#pragma unroll
    for (int c = 0; c < STAGES - 1; ++c) {
        const uint32_t st = sbase + c * STAGE_BYTES;
        const int kc = c * BK;
#pragma unroll
        for (int i = 0; i < 8; ++i) {
            CP_ASYNC16(st + sAB[i],                  Ap + oA[i] + kc);      // Ahi
            CP_ASYNC16(st + TILE_BYTES   + sAB[i],   Ap + oA[i] + K + kc);  // Alo
            CP_ASYNC16(st + 2*TILE_BYTES + sAB[i],   Bp + oB[i] + kc);      // Bhi
            CP_ASYNC16(st + 3*TILE_BYTES + sAB[i],   Bp + oB[i] + K + kc);  // Blo
        }
        CP_ASYNC_COMMIT();
    }

    // ---- ldmatrix addressing ----------------------------------------------
    uint32_t aRow[4], aXm[4];
    const uint32_t aCol = (uint32_t)(lane >> 4) << 4;
#pragma unroll
    for (int mi = 0; mi < 4; ++mi) {
        int r = warp_m + mi * 16 + (lane & 15);
        aRow[mi] = (uint32_t)r << 7;
        aXm[mi]  = (uint32_t)(r & 7) << 4;
    }
    // B paired x4: pair p covers ni = 2p, 2p+1
    uint32_t bRowP[4], bXmP[4];
    const uint32_t bCol = (uint32_t)((lane >> 3) & 1) << 4;
#pragma unroll
    for (int p = 0; p < 4; ++p) {
        int r = warp_n + (2 * p + ((lane >> 4) & 1)) * 8 + (lane & 7);
        bRowP[p] = (uint32_t)r << 7;
        bXmP[p]  = (uint32_t)(r & 7) << 4;
    }

    // ---- mainloop ----------------------------------------------------------
    int s = 0;
    for (int c = 0; c < nChunks; ++c) {
        CP_ASYNC_WAIT(STAGES - 2);
        __syncthreads();

        const uint32_t stAhi = sbase + s * STAGE_BYTES;
        const uint32_t stAlo = stAhi + TILE_BYTES;
        const uint32_t stBhi = stAhi + 2 * TILE_BYTES;
        const uint32_t stBlo = stAhi + 3 * TILE_BYTES;

#pragma unroll
        for (int kk = 0; kk < 4; ++kk) {
            const uint32_t kb = (uint32_t)kk << 5;
            uint32_t ah[4][4], al[4][4], bh[8][2], bl[8][2];
            // load ah, bh, bl first; do ah-terms; then al and al-term
#pragma unroll
            for (int mi = 0; mi < 4; ++mi) {
                uint32_t xo = (kb + aCol);
                LDMATRIX_X4(ah[mi][0], ah[mi][1], ah[mi][2], ah[mi][3],
                            stAhi + aRow[mi] + (xo ^ aXm[mi]));
            }
#pragma unroll
            for (int p = 0; p < 4; ++p) {
                uint32_t xo = (kb + bCol);
                LDMATRIX_X4(bh[2*p][0], bh[2*p][1], bh[2*p+1][0], bh[2*p+1][1],
                            stBhi + bRowP[p] + (xo ^ bXmP[p]));
                LDMATRIX_X4(bl[2*p][0], bl[2*p][1], bl[2*p+1][0], bl[2*p+1][1],
                            stBlo + bRowP[p] + (xo ^ bXmP[p]));
            }
#pragma unroll
            for (int mi = 0; mi < 4; ++mi)
#pragma unroll
                for (int ni = 0; ni < 8; ++ni) {
                    mma_bf16(acc[mi][ni], ah[mi], bh[ni]);
                    mma_bf16(acc[mi][ni], ah[mi], bl[ni]);
                }
#pragma unroll
            for (int mi = 0; mi < 4; ++mi) {
                uint32_t xo = (kb + aCol);
                LDMATRIX_X4(al[mi][0], al[mi][1], al[mi][2], al[mi][3],
                            stAlo + aRow[mi] + (xo ^ aXm[mi]));
            }
#pragma unroll
            for (int mi = 0; mi < 4; ++mi)
#pragma unroll
                for (int ni = 0; ni < 8; ++ni)
                    mma_bf16(acc[mi][ni], al[mi], bh[ni]);
        }

        const int cn = c + STAGES - 1;
        if (cn < nChunks) {
            int sn = s + (STAGES - 1); if (sn >= STAGES) sn -= STAGES;
            const uint32_t st = sbase + sn * STAGE_BYTES;
            const int kc = cn * BK;
#pragma unroll
            for (int i = 0; i < 8; ++i) {
                CP_ASYNC16(st + sAB[i],                Ap + oA[i] + kc);
                CP_ASYNC16(st + TILE_BYTES   + sAB[i], Ap + oA[i] + K + kc);
                CP_ASYNC16(st + 2*TILE_BYTES + sAB[i], Bp + oB[i] + kc);
                CP_ASYNC16(st + 3*TILE_BYTES + sAB[i], Bp + oB[i] + K + kc);
            }
        }
        CP_ASYNC_COMMIT();
        if (++s == STAGES) s = 0;
    }

    // ---- epilogue ----------------------------------------------------------
    CP_ASYNC_WAIT(0);
    __syncthreads();

    float* bias_s = reinterpret_cast<float*>(smem);                // [128]
    float* Us     = reinterpret_cast<float*>(smem + 1024);         // [8][128]
    float* Ps     = reinterpret_cast<float*>(smem + 1024 + 4096);  // [128][8]
    float* Dsn    = reinterpret_cast<float*>(smem + 1024 + 8192);  // [128][8]
    float* sPP    = reinterpret_cast<float*>(smem + 16384);        // [2][128][8]

    bias_s[tid] = bias[nBase + tid];
#pragma unroll
    for (int i = 0; i < 8; ++i) {
        int idx = tid + (i << 7);
        int r = idx >> 7, n = idx & 127;
        Us[idx] = U[((size_t)r * N + nBase + n) * T_TASKS + task];
    }
    {
        const float* pr0 = P + (size_t)(mBase + tid) * RNK;
        float4 v0 = *reinterpret_cast<const float4*>(pr0);
        float4 v1 = *reinterpret_cast<const float4*>(pr0 + 4);
        *reinterpret_cast<float4*>(&Ps[tid * RNK])     = v0;
        *reinterpret_cast<float4*>(&Ps[tid * RNK + 4]) = v1;
    }
    if (mode == 1) {
#pragma unroll
        for (int i = 0; i < 8; ++i) {
            int idx = tid + (i << 7);
            int n = idx >> 3, r = idx & 7;
            Dsn[idx] = Dn[(size_t)(nBase + n) * 64 + r * 8 + task];
        }
    }
    __syncthreads();

#pragma unroll
    for (int mi = 0; mi < 4; ++mi) {
#pragma unroll
        for (int half = 0; half < 2; ++half) {
            const int rloc = warp_m + mi * 16 + (lane >> 2) + half * 8;
            const int gm   = mBase + rloc;
            float pr[RNK];
            {
                float4 p0 = *reinterpret_cast<const float4*>(&Ps[rloc * RNK]);
                float4 p1 = *reinterpret_cast<const float4*>(&Ps[rloc * RNK + 4]);
                pr[0]=p0.x; pr[1]=p0.y; pr[2]=p0.z; pr[3]=p0.w;
                pr[4]=p1.x; pr[5]=p1.y; pr[6]=p1.z; pr[7]=p1.w;
            }
            float pp[RNK];
#pragma unroll
            for (int r = 0; r < RNK; ++r) pp[r] = 0.f;

#pragma unroll
            for (int ni = 0; ni < 8; ++ni) {
                const int nloc = warp_n + ni * 8 + ((lane & 3) << 1);
                float l0 = 0.f, l1 = 0.f;
#pragma unroll
                for (int q = 0; q < RNK; ++q) {
                    l0 += pr[q] * Us[(q << 7) + nloc];
                    l1 += pr[q] * Us[(q << 7) + nloc + 1];
                }
                float v0 = acc[mi][ni][half * 2 + 0] + bias_s[nloc]     + 2.f * l0;
                float v1 = acc[mi][ni][half * 2 + 1] + bias_s[nloc + 1] + 2.f * l1;
                if (mode == 1) {
                    v0 = fmaxf(v0, 0.f); v1 = fmaxf(v1, 0.f);
                    __nv_bfloat16 h0 = __float2bfloat16(v0);
                    __nv_bfloat16 h1 = __float2bfloat16(v1);
                    __nv_bfloat16 lo0 = __float2bfloat16(v0 - __bfloat162float(h0));
                    __nv_bfloat16 lo1 = __float2bfloat16(v1 - __bfloat162float(h1));
                    __nv_bfloat16* orow = (__nv_bfloat16*)Cp +
                        (size_t)gm * (2 * N) + nBase + nloc;
                    __nv_bfloat162 hv; hv.x = h0; hv.y = h1;
                    __nv_bfloat162 lv; lv.x = lo0; lv.y = lo1;
                    *reinterpret_cast<__nv_bfloat162*>(orow)     = hv;
                    *reinterpret_cast<__nv_bfloat162*>(orow + N) = lv;
#pragma unroll
                    for (int r = 0; r < RNK; ++r)
                        pp[r] += v0 * Dsn[(nloc << 3) + r]
                               + v1 * Dsn[((nloc + 1) << 3) + r];
                } else {
                    float* crow = (float*)Cp + (size_t)gm * N + nBase + nloc;
                    *reinterpret_cast<float2*>(crow) = make_float2(v0, v1);
                }
            }

            if (mode == 1) {
                // reduce across the quad (4 lanes share rloc)
#pragma unroll
                for (int r = 0; r < RNK; ++r) {
                    pp[r] += __shfl_xor_sync(0xffffffffu, pp[r], 1);
                    pp[r] += __shfl_xor_sync(0xffffffffu, pp[r], 2);
                }
                // per-n-warp slot (wid&1); both m-groups write disjoint rows
                if ((lane & 3) == 0) {
                    float* dst = &sPP[(((wid & 1) << 7) + rloc) * RNK];
#pragma unroll
                    for (int r = 0; r < RNK; ++r) dst[r] = pp[r];
                }
            }
        }
    }

    if (mode == 1) {
        __syncthreads();
        // sum the 2 warp-n slots -> one deterministic partial per block
        for (int i = tid; i < BM * RNK; i += NTHR) {
            float sum = sPP[i] + sPP[1024 + i];
            Pp[(size_t)blockIdx.x * (M_ROWS * RNK) + (size_t)mBase * RNK + i] = sum;
        }
    }
}

// ---------------------------------------------------------------------------
// Host launcher
// ---------------------------------------------------------------------------
extern "C" void kernel_launch(void* const* d_in, const int* in_sizes, int n_in,
                              void* d_out, int out_size)
{
    const float* x  = (const float*)d_in[0];
    const float* k0 = (const float*)d_in[1];
    const float* b0 = (const float*)d_in[2];
    const float* d0 = (const float*)d_in[3];
    const float* u0 = (const float*)d_in[4];
    const float* k1 = (const float*)d_in[5];
    const float* b1 = (const float*)d_in[6];
    const float* d1 = (const float*)d_in[7];
    const float* u1 = (const float*)d_in[8];
    const float* k2 = (const float*)d_in[9];
    const float* b2 = (const float*)d_in[10];
    const float* d2 = (const float*)d_in[11];
    const float* u2 = (const float*)d_in[12];
    float* out = (float*)d_out;

    __nv_bfloat16 *a0, *a1, *bS;
    float *p, *pp;
    cudaGetSymbolAddress((void**)&a0, g_A0);
    cudaGetSymbolAddress((void**)&a1, g_A1);
    cudaGetSymbolAddress((void**)&bS, g_B);
    cudaGetSymbolAddress((void**)&p,  g_p);
    cudaGetSymbolAddress((void**)&pp, g_pp);

    cudaFuncSetAttribute(gemm_mma_kernel,
                         cudaFuncAttributeMaxDynamicSharedMemorySize, SMEM_BYTES);

    // layer-0 prep: x -> A0 [hi|lo] + P0, single pass over x
    prep0_kernel<<<M_ROWS / 8, 256>>>(x, d0, a0, p);

    // layer 0: A0[.,1024] -> A1[.,2048] bf16+ReLU, fused P' partials (d1)
    convertW_kernel<<<dim3(2048 / 32, 1024 / 32), 256>>>(k0, bS, 1024, 2048);
    gemm_mma_kernel<<<dim3(2048 / BN, M_ROWS / BM), NTHR, SMEM_BYTES>>>(
        a0, bS, b0, p, u0, a1, d1, pp, 1024, 2048, 1);
    reduceP_kernel<<<(M_ROWS * RNK) / 256, 256>>>(pp, p, 2048 / BN);

    // layer 1: A1[.,2048] -> A0[.,2048] bf16+ReLU, fused P' partials (d2)
    convertW_kernel<<<dim3(2048 / 32, 2048 / 32), 256>>>(k1, bS, 2048, 2048);
    gemm_mma_kernel<<<dim3(2048 / BN, M_ROWS / BM), NTHR, SMEM_BYTES>>>(
        a1, bS, b1, p, u1, a0, d2, pp, 2048, 2048, 1);
    reduceP_kernel<<<(M_ROWS * RNK) / 256, 256>>>(pp, p, 2048 / BN);

    // layer 2: A0[.,2048] -> out fp32 [.,1024], no ReLU
    convertW_kernel<<<dim3(1024 / 32, 2048 / 32), 256>>>(k2, bS, 2048, 1024);
    gemm_mma_kernel<<<dim3(1024 / BN, M_ROWS / BM), NTHR, SMEM_BYTES>>>(
        a0, bS, b2, p, u2, out, nullptr, nullptr, 2048, 1024, 0);
}

// round 12
// speedup vs baseline: 1.5907x; 1.5907x over previous
#include <cuda_runtime.h>
#include <cuda_fp16.h>
#include <cstdint>

// ---------------------------------------------------------------------------
// LoRA multi-task MLP via mma.sync fp16 (plain sm_100 target).
// Precision scheme (round 12): W split into fp16 hi+lo (22 mantissa bits,
// static, done once); activations single fp16 (error 2^-11 -> ~5e-4 total).
// GEMM: acc = A*Whi + A*Wlo (2 MMA terms per chunk, SAME A fragments).
// Geometry = R6 champion: BM=BN=128, BK=64, 3 stages, 8 warps (2m x 4n),
// warp tile 64x32, 1 CTA/SM. Fused epilogue: bias + 2*P*U + ReLU + fp16
// store + race-free next-layer LoRA-down partials.
// ---------------------------------------------------------------------------

#define T_TASKS 8
#define RNK 8
#define M_ROWS 8192

#define BM 128
#define BN 128
#define BK 64                          // K elements per chunk (128 B fp16 rows)
#define STAGES 3
#define TILE_BYTES (128 * 128)         // 16 KB per operand tile
#define STAGE_BYTES (3 * TILE_BYTES)   // A | Whi | Wlo = 48 KB
#define SMEM_BYTES (STAGES * STAGE_BYTES)   // 144 KB

// ---- scratch (device globals; no allocation allowed) ----------------------
__device__ __half g_A0[(size_t)M_ROWS * 2048];   // fp16 activations, 32 MB
__device__ __half g_A1[(size_t)M_ROWS * 2048];   // fp16 activations, 32 MB
__device__ __half g_B [(size_t)2048   * 4096];   // [Whi|Wlo] fp16, 16 MB
__device__ float g_p [M_ROWS * RNK];
__device__ float g_pp[16 * M_ROWS * RNK];        // per-n-block partials

// ---------------------------------------------------------------------------
__device__ __forceinline__ uint32_t smem_u32(const void* p) {
    uint32_t a;
    asm("{ .reg .u64 t; cvta.to.shared.u64 t, %1; cvt.u32.u64 %0, t; }"
        : "=r"(a) : "l"(p));
    return a;
}

#define CP_ASYNC16(smem, gptr) \
    asm volatile("cp.async.cg.shared.global [%0], [%1], 16;" \
                 :: "r"(smem), "l"(gptr) : "memory")
#define CP_ASYNC_COMMIT() asm volatile("cp.async.commit_group;" ::: "memory")
#define CP_ASYNC_WAIT(n)  asm volatile("cp.async.wait_group %0;" :: "n"(n) : "memory")

#define LDMATRIX_X4(r0,r1,r2,r3,addr) \
    asm volatile("ldmatrix.sync.aligned.m8n8.x4.shared.b16 {%0,%1,%2,%3}, [%4];" \
        : "=r"(r0),"=r"(r1),"=r"(r2),"=r"(r3) : "r"(addr))

__device__ __forceinline__ void mma_fp16(float* c, const uint32_t* a,
                                         const uint32_t* b) {
    asm volatile(
        "mma.sync.aligned.m16n8k16.row.col.f32.f16.f16.f32 "
        "{%0,%1,%2,%3}, {%4,%5,%6,%7}, {%8,%9}, {%0,%1,%2,%3};"
        : "+f"(c[0]), "+f"(c[1]), "+f"(c[2]), "+f"(c[3])
        : "r"(a[0]), "r"(a[1]), "r"(a[2]), "r"(a[3]), "r"(b[0]), "r"(b[1]));
}

// ---------------------------------------------------------------------------
// Fused layer-0 prep: x fp32 -> A0 fp16 AND P0[m,r] = x·D0[:,r,t].
// One block = 8 rows (one warp per row). K = 1024 fixed.
// ---------------------------------------------------------------------------
__global__ __launch_bounds__(256)
void prep0_kernel(const float* __restrict__ x, const float* __restrict__ D,
                  __half* __restrict__ Ap, float* __restrict__ P)
{
    __shared__ float Ds[RNK][1024];
    const int tid  = threadIdx.x;
    const int wid  = tid >> 5;
    const int lane = tid & 31;
    const int row  = blockIdx.x * 8 + wid;
    const int t    = (blockIdx.x * 8) >> 10;

    for (int idx = tid; idx < 1024 * RNK; idx += 256) {
        int k = idx >> 3, r = idx & 7;
        Ds[r][k] = D[(size_t)k * 64 + r * 8 + t];
    }
    __syncthreads();

    const float4* xr = reinterpret_cast<const float4*>(x + (size_t)row * 1024);
    __half* arow = Ap + (size_t)row * 1024;
    float acc[RNK];
#pragma unroll
    for (int r = 0; r < RNK; ++r) acc[r] = 0.f;
#pragma unroll
    for (int i = 0; i < 8; ++i) {
        int kq = lane + 32 * i;
        float4 v = xr[kq];
        int k = kq << 2;
        union { __half h[4]; uint2 u; } hp;
        hp.h[0] = __float2half(v.x);
        hp.h[1] = __float2half(v.y);
        hp.h[2] = __float2half(v.z);
        hp.h[3] = __float2half(v.w);
        *reinterpret_cast<uint2*>(arow + k) = hp.u;
#pragma unroll
        for (int r = 0; r < RNK; ++r) {
            float4 d = *reinterpret_cast<const float4*>(&Ds[r][k]);
            acc[r] += v.x * d.x + v.y * d.y + v.z * d.z + v.w * d.w;
        }
    }
#pragma unroll
    for (int r = 0; r < RNK; ++r) {
        float v = acc[r];
#pragma unroll
        for (int o = 16; o > 0; o >>= 1) v += __shfl_down_sync(0xffffffffu, v, o);
        if (lane == 0) P[(size_t)row * RNK + r] = v;
    }
}

// ---------------------------------------------------------------------------
// P[m,r] = sum_nb Pp[nb][m][r]
// ---------------------------------------------------------------------------
__global__ __launch_bounds__(256)
void reduceP_kernel(const float* __restrict__ Pp, float* __restrict__ P, int nb)
{
    int i = blockIdx.x * 256 + threadIdx.x;      // over M_ROWS*RNK = 65536
    float s = 0.f;
    for (int b = 0; b < nb; ++b) s += Pp[(size_t)b * (M_ROWS * RNK) + i];
    P[i] = s;
}

// ---------------------------------------------------------------------------
// W[K,N] fp32 -> B'[N,2K] fp16 = [Whi^T | Wlo^T]  (Wlo = fp16(W - Whi))
// ---------------------------------------------------------------------------
__global__ __launch_bounds__(256)
void convertW_kernel(const float* __restrict__ W, __half* __restrict__ Bp,
                     int K, int N)
{
    __shared__ float t[32][33];
    int n0 = blockIdx.x * 32, k0 = blockIdx.y * 32;
    int tx = threadIdx.x & 31, ty = threadIdx.x >> 5;   // 32 x 8
#pragma unroll
    for (int i = 0; i < 4; ++i)
        t[ty + 8 * i][tx] = W[(size_t)(k0 + ty + 8 * i) * N + n0 + tx];
    __syncthreads();
#pragma unroll
    for (int i = 0; i < 4; ++i) {
        int nn = ty + 8 * i;
        float v = t[tx][nn];
        __half h = __float2half(v);
        __half l = __float2half(v - __half2float(h));
        size_t rb = (size_t)(n0 + nn) * 2 * K + k0 + tx;
        Bp[rb]     = h;
        Bp[rb + K] = l;
    }
}

// ---------------------------------------------------------------------------
// 3-stage pipelined fp16 mma.sync GEMM (R6 geometry), 2 terms per chunk:
//   acc = A*Whi + A*Wlo   (same A fragments, fp32 accumulate)
// Fused epilogue + race-free next-layer LoRA-down partials.
// mode==1: fp16 output (stride N) + ReLU + fused P partials (Dn).
// mode==0: fp32 output (stride N), no ReLU, no P partials.
// ---------------------------------------------------------------------------
__global__ __launch_bounds__(256, 1)
void gemm_mma_kernel(const __half* __restrict__ Ap,
                     const __half* __restrict__ Bp,
                     const float* __restrict__ bias,
                     const float* __restrict__ P,
                     const float* __restrict__ U,
                     void* __restrict__ Cp,
                     const float* __restrict__ Dn,   // next-layer D or null
                     float* __restrict__ Pp,         // partial buffer or null
                     int K, int N, int mode)
{
    extern __shared__ char smem[];
    const uint32_t sbase = smem_u32(smem);
    const int tid  = threadIdx.x;
    const int wid  = tid >> 5;
    const int lane = tid & 31;
    const int mBase = blockIdx.y * BM;
    const int nBase = blockIdx.x * BN;
    const int task  = mBase >> 10;
    const uint32_t ldW = 2 * (uint32_t)K;     // W' row stride
    const int nChunks = K / BK;

    const int warp_m = (wid >> 2) * 64;   // 0 / 64
    const int warp_n = (wid & 3) * 32;    // 0 / 32 / 64 / 96

    // ---- producer addressing: 4 granules per tile per thread ---------------
    const __half* gA[4];
    const __half* gB[4];
    uint32_t sAB[4];
#pragma unroll
    for (int i = 0; i < 4; ++i) {
        int g = tid + (i << 8);           // 16B granule id 0..1023
        int r = g >> 3, q = g & 7;        // row 0..127, 16B col 0..7
        uint32_t off = (uint32_t)(r << 7) + (q << 4);
        sAB[i] = off ^ ((uint32_t)(r & 7) << 4);
        gA[i] = Ap + (size_t)(mBase + r) * (uint32_t)K + (q << 3);
        gB[i] = Bp + (size_t)(nBase + r) * ldW + (q << 3);
    }

    float acc[4][4][4];
#pragma unroll
    for (int mi = 0; mi < 4; ++mi)
#pragma unroll
        for (int ni = 0; ni < 4; ++ni)
#pragma unroll
            for (int j = 0; j < 4; ++j) acc[mi][ni][j] = 0.f;

    // ---- prologue: fill STAGES-1 stages -----------------------------------
#pragma unroll
    for (int c = 0; c < STAGES - 1; ++c) {
        const uint32_t st = sbase + c * STAGE_BYTES;
        const int kc = c * BK;
#pragma unroll
        for (int i = 0; i < 4; ++i) {
            CP_ASYNC16(st + sAB[i],                  gA[i] + kc);      // A
            CP_ASYNC16(st + TILE_BYTES   + sAB[i],   gB[i] + kc);      // Whi
            CP_ASYNC16(st + 2*TILE_BYTES + sAB[i],   gB[i] + K + kc);  // Wlo
        }
        CP_ASYNC_COMMIT();
    }

    // ---- ldmatrix addressing ----------------------------------------------
    uint32_t aRow[4], aXm[4];
    const uint32_t aCol = (uint32_t)(lane >> 4) << 4;
#pragma unroll
    for (int mi = 0; mi < 4; ++mi) {
        int r = warp_m + mi * 16 + (lane & 15);
        aRow[mi] = (uint32_t)r << 7;
        aXm[mi]  = (uint32_t)(r & 7) << 4;
    }
    // B paired x4: pair p covers ni = 2p, 2p+1 (validated round 10)
    uint32_t bRowP[2], bXmP[2];
    const uint32_t bCol = (uint32_t)((lane >> 3) & 1) << 4;
#pragma unroll
    for (int p = 0; p < 2; ++p) {
        int r = warp_n + (2 * p + ((lane >> 4) & 1)) * 8 + (lane & 7);
        bRowP[p] = (uint32_t)r << 7;
        bXmP[p]  = (uint32_t)(r & 7) << 4;
    }

    // ---- mainloop ----------------------------------------------------------
    int s = 0;
    for (int c = 0; c < nChunks; ++c) {
        CP_ASYNC_WAIT(STAGES - 2);
        __syncthreads();

        const uint32_t stA  = sbase + s * STAGE_BYTES;
        const uint32_t stHi = stA + TILE_BYTES;
        const uint32_t stLo = stA + 2 * TILE_BYTES;

#pragma unroll
        for (int kk = 0; kk < 4; ++kk) {
            const uint32_t kb = (uint32_t)kk << 5;
            uint32_t a[4][4], bh[4][2], bl[4][2];
#pragma unroll
            for (int mi = 0; mi < 4; ++mi) {
                uint32_t xo = (kb + aCol);
                LDMATRIX_X4(a[mi][0], a[mi][1], a[mi][2], a[mi][3],
                            stA + aRow[mi] + (xo ^ aXm[mi]));
            }
#pragma unroll
            for (int p = 0; p < 2; ++p) {
                uint32_t xo = (kb + bCol);
                LDMATRIX_X4(bh[2*p][0], bh[2*p][1], bh[2*p+1][0], bh[2*p+1][1],
                            stHi + bRowP[p] + (xo ^ bXmP[p]));
                LDMATRIX_X4(bl[2*p][0], bl[2*p][1], bl[2*p+1][0], bl[2*p+1][1],
                            stLo + bRowP[p] + (xo ^ bXmP[p]));
            }
#pragma unroll
            for (int mi = 0; mi < 4; ++mi)
#pragma unroll
                for (int ni = 0; ni < 4; ++ni) {
                    mma_fp16(acc[mi][ni], a[mi], bh[ni]);
                    mma_fp16(acc[mi][ni], a[mi], bl[ni]);
                }
        }

        const int cn = c + STAGES - 1;
        if (cn < nChunks) {
            int sn = s + (STAGES - 1); if (sn >= STAGES) sn -= STAGES;
            const uint32_t st = sbase + sn * STAGE_BYTES;
            const int kc = cn * BK;
#pragma unroll
            for (int i = 0; i < 4; ++i) {
                CP_ASYNC16(st + sAB[i],                gA[i] + kc);
                CP_ASYNC16(st + TILE_BYTES   + sAB[i], gB[i] + kc);
                CP_ASYNC16(st + 2*TILE_BYTES + sAB[i], gB[i] + K + kc);
            }
        }
        CP_ASYNC_COMMIT();
        if (++s == STAGES) s = 0;
    }

    // ---- epilogue ----------------------------------------------------------
    CP_ASYNC_WAIT(0);
    __syncthreads();

    float* bias_s = reinterpret_cast<float*>(smem);                // [128]
    float* Us     = reinterpret_cast<float*>(smem + 1024);         // [8][128]
    float* Ps     = reinterpret_cast<float*>(smem + 1024 + 4096);  // [128][8]
    float* Dsn    = reinterpret_cast<float*>(smem + 1024 + 8192);  // [128][8]
    float* sPP    = reinterpret_cast<float*>(smem + 16384);        // [4][128][8]

    if (tid < BN) bias_s[tid] = bias[nBase + tid];
#pragma unroll
    for (int i = 0; i < 4; ++i) {
        int idx = tid + (i << 8);
        int r = idx >> 7, n = idx & 127;
        Us[idx] = U[((size_t)r * N + nBase + n) * T_TASKS + task];
    }
    {
        int row = tid >> 1, half = (tid & 1) << 2;
        float4 v = *reinterpret_cast<const float4*>(
            P + (size_t)(mBase + row) * RNK + half);
        *reinterpret_cast<float4*>(&Ps[row * RNK + half]) = v;
    }
    if (mode == 1) {
#pragma unroll
        for (int i = 0; i < 4; ++i) {
            int idx = tid + (i << 8);
            int n = idx >> 3, r = idx & 7;
            Dsn[idx] = Dn[(size_t)(nBase + n) * 64 + r * 8 + task];
        }
    }
    __syncthreads();

#pragma unroll
    for (int mi = 0; mi < 4; ++mi) {
#pragma unroll
        for (int half = 0; half < 2; ++half) {
            const int rloc = warp_m + mi * 16 + (lane >> 2) + half * 8;
            const int gm   = mBase + rloc;
            float pr[RNK];
            {
                float4 p0 = *reinterpret_cast<const float4*>(&Ps[rloc * RNK]);
                float4 p1 = *reinterpret_cast<const float4*>(&Ps[rloc * RNK + 4]);
                pr[0]=p0.x; pr[1]=p0.y; pr[2]=p0.z; pr[3]=p0.w;
                pr[4]=p1.x; pr[5]=p1.y; pr[6]=p1.z; pr[7]=p1.w;
            }
            float pp[RNK];
#pragma unroll
            for (int r = 0; r < RNK; ++r) pp[r] = 0.f;

#pragma unroll
            for (int ni = 0; ni < 4; ++ni) {
                const int nloc = warp_n + ni * 8 + ((lane & 3) << 1);
                float l0 = 0.f, l1 = 0.f;
#pragma unroll
                for (int q = 0; q < RNK; ++q) {
                    l0 += pr[q] * Us[(q << 7) + nloc];
                    l1 += pr[q] * Us[(q << 7) + nloc + 1];
                }
                float v0 = acc[mi][ni][half * 2 + 0] + bias_s[nloc]     + 2.f * l0;
                float v1 = acc[mi][ni][half * 2 + 1] + bias_s[nloc + 1] + 2.f * l1;
                if (mode == 1) {
                    v0 = fmaxf(v0, 0.f); v1 = fmaxf(v1, 0.f);
                    __half2 hv;
                    hv.x = __float2half(v0);
                    hv.y = __float2half(v1);
                    __half* orow = (__half*)Cp + (size_t)gm * N + nBase + nloc;
                    *reinterpret_cast<__half2*>(orow) = hv;
#pragma unroll
                    for (int r = 0; r < RNK; ++r)
                        pp[r] += v0 * Dsn[(nloc << 3) + r]
                               + v1 * Dsn[((nloc + 1) << 3) + r];
                } else {
                    float* crow = (float*)Cp + (size_t)gm * N + nBase + nloc;
                    *reinterpret_cast<float2*>(crow) = make_float2(v0, v1);
                }
            }

            if (mode == 1) {
                // reduce across the quad (4 lanes share rloc)
#pragma unroll
                for (int r = 0; r < RNK; ++r) {
                    pp[r] += __shfl_xor_sync(0xffffffffu, pp[r], 1);
                    pp[r] += __shfl_xor_sync(0xffffffffu, pp[r], 2);
                }
                // per-warp slot (wid&3 = n-group); disjoint rows per slot
                if ((lane & 3) == 0) {
                    float* dst = &sPP[(((wid & 3) << 7) + rloc) * RNK];
#pragma unroll
                    for (int r = 0; r < RNK; ++r) dst[r] = pp[r];
                }
            }
        }
    }

    if (mode == 1) {
        __syncthreads();
        // sum the 4 warp-n slots -> one deterministic partial per block
        for (int i = tid; i < BM * RNK; i += 256) {
            float sum = sPP[i] + sPP[1024 + i] + sPP[2048 + i] + sPP[3072 + i];
            Pp[(size_t)blockIdx.x * (M_ROWS * RNK) + (size_t)mBase * RNK + i] = sum;
        }
    }
}

// ---------------------------------------------------------------------------
// Host launcher
// ---------------------------------------------------------------------------
extern "C" void kernel_launch(void* const* d_in, const int* in_sizes, int n_in,
                              void* d_out, int out_size)
{
    const float* x  = (const float*)d_in[0];
    const float* k0 = (const float*)d_in[1];
    const float* b0 = (const float*)d_in[2];
    const float* d0 = (const float*)d_in[3];
    const float* u0 = (const float*)d_in[4];
    const float* k1 = (const float*)d_in[5];
    const float* b1 = (const float*)d_in[6];
    const float* d1 = (const float*)d_in[7];
    const float* u1 = (const float*)d_in[8];
    const float* k2 = (const float*)d_in[9];
    const float* b2 = (const float*)d_in[10];
    const float* d2 = (const float*)d_in[11];
    const float* u2 = (const float*)d_in[12];
    float* out = (float*)d_out;

    __half *a0, *a1, *bS;
    float *p, *pp;
    cudaGetSymbolAddress((void**)&a0, g_A0);
    cudaGetSymbolAddress((void**)&a1, g_A1);
    cudaGetSymbolAddress((void**)&bS, g_B);
    cudaGetSymbolAddress((void**)&p,  g_p);
    cudaGetSymbolAddress((void**)&pp, g_pp);

    cudaFuncSetAttribute(gemm_mma_kernel,
                         cudaFuncAttributeMaxDynamicSharedMemorySize, SMEM_BYTES);

    // layer-0 prep: x -> A0 fp16 + P0, single pass over x
    prep0_kernel<<<M_ROWS / 8, 256>>>(x, d0, a0, p);

    // layer 0: A0[.,1024] -> A1[.,2048] fp16+ReLU, fused P' partials (d1)
    convertW_kernel<<<dim3(2048 / 32, 1024 / 32), 256>>>(k0, bS, 1024, 2048);
    gemm_mma_kernel<<<dim3(2048 / BN, M_ROWS / BM), 256, SMEM_BYTES>>>(
        a0, bS, b0, p, u0, a1, d1, pp, 1024, 2048, 1);
    reduceP_kernel<<<(M_ROWS * RNK) / 256, 256>>>(pp, p, 2048 / BN);

    // layer 1: A1[.,2048] -> A0[.,2048] fp16+ReLU, fused P' partials (d2)
    convertW_kernel<<<dim3(2048 / 32, 2048 / 32), 256>>>(k1, bS, 2048, 2048);
    gemm_mma_kernel<<<dim3(2048 / BN, M_ROWS / BM), 256, SMEM_BYTES>>>(
        a1, bS, b1, p, u1, a0, d2, pp, 2048, 2048, 1);
    reduceP_kernel<<<(M_ROWS * RNK) / 256, 256>>>(pp, p, 2048 / BN);

    // layer 2: A0[.,2048] -> out fp32 [.,1024], no ReLU
    convertW_kernel<<<dim3(1024 / 32, 2048 / 32), 256>>>(k2, bS, 2048, 1024);
    gemm_mma_kernel<<<dim3(1024 / BN, M_ROWS / BM), 256, SMEM_BYTES>>>(
        a0, bS, b2, p, u2, out, nullptr, nullptr, 2048, 1024, 0);
}

// round 13
// speedup vs baseline: 2.3774x; 1.4945x over previous
#include <cuda_runtime.h>
#include <cuda_fp16.h>
#include <cstdint>

// ---------------------------------------------------------------------------
// LoRA multi-task MLP via mma.sync fp16 (plain sm_100 target).
// Round 13: plain single-term fp16 GEMM (acc = A*W, fp32 accumulate).
// Error budget: A and W each rounded to fp16 (2^-11); measured A-only error
// was 3.6e-4, adding W gives ~sqrt(2)x = ~5.1e-4 < 1e-3 gate.
// Geometry = champion: BM=BN=128, BK=64, 3 stages, 8 warps (2m x 4n),
// warp tile 64x32, 1 CTA/SM. Fused epilogue: bias + 2*P*U + ReLU + fp16
// store + race-free next-layer LoRA-down partials.
// ---------------------------------------------------------------------------

#define T_TASKS 8
#define RNK 8
#define M_ROWS 8192

#define BM 128
#define BN 128
#define BK 64                          // K elements per chunk (128 B fp16 rows)
#define STAGES 3
#define TILE_BYTES (128 * 128)         // 16 KB per operand tile
#define STAGE_BYTES (2 * TILE_BYTES)   // A | W = 32 KB
#define SMEM_BYTES (STAGES * STAGE_BYTES)   // 96 KB

// ---- scratch (device globals; no allocation allowed) ----------------------
__device__ __half g_A0[(size_t)M_ROWS * 2048];   // fp16 activations, 32 MB
__device__ __half g_A1[(size_t)M_ROWS * 2048];   // fp16 activations, 32 MB
__device__ __half g_B [(size_t)2048   * 2048];   // W^T fp16, 8 MB
__device__ float g_p [M_ROWS * RNK];
__device__ float g_pp[16 * M_ROWS * RNK];        // per-n-block partials

// ---------------------------------------------------------------------------
__device__ __forceinline__ uint32_t smem_u32(const void* p) {
    uint32_t a;
    asm("{ .reg .u64 t; cvta.to.shared.u64 t, %1; cvt.u32.u64 %0, t; }"
        : "=r"(a) : "l"(p));
    return a;
}

#define CP_ASYNC16(smem, gptr) \
    asm volatile("cp.async.cg.shared.global [%0], [%1], 16;" \
                 :: "r"(smem), "l"(gptr) : "memory")
#define CP_ASYNC_COMMIT() asm volatile("cp.async.commit_group;" ::: "memory")
#define CP_ASYNC_WAIT(n)  asm volatile("cp.async.wait_group %0;" :: "n"(n) : "memory")

#define LDMATRIX_X4(r0,r1,r2,r3,addr) \
    asm volatile("ldmatrix.sync.aligned.m8n8.x4.shared.b16 {%0,%1,%2,%3}, [%4];" \
        : "=r"(r0),"=r"(r1),"=r"(r2),"=r"(r3) : "r"(addr))

__device__ __forceinline__ void mma_fp16(float* c, const uint32_t* a,
                                         const uint32_t* b) {
    asm volatile(
        "mma.sync.aligned.m16n8k16.row.col.f32.f16.f16.f32 "
        "{%0,%1,%2,%3}, {%4,%5,%6,%7}, {%8,%9}, {%0,%1,%2,%3};"
        : "+f"(c[0]), "+f"(c[1]), "+f"(c[2]), "+f"(c[3])
        : "r"(a[0]), "r"(a[1]), "r"(a[2]), "r"(a[3]), "r"(b[0]), "r"(b[1]));
}

// ---------------------------------------------------------------------------
// Fused layer-0 prep: x fp32 -> A0 fp16 AND P0[m,r] = x·D0[:,r,t].
// ---------------------------------------------------------------------------
__global__ __launch_bounds__(256)
void prep0_kernel(const float* __restrict__ x, const float* __restrict__ D,
                  __half* __restrict__ Ap, float* __restrict__ P)
{
    __shared__ float Ds[RNK][1024];
    const int tid  = threadIdx.x;
    const int wid  = tid >> 5;
    const int lane = tid & 31;
    const int row  = blockIdx.x * 8 + wid;
    const int t    = (blockIdx.x * 8) >> 10;

    for (int idx = tid; idx < 1024 * RNK; idx += 256) {
        int k = idx >> 3, r = idx & 7;
        Ds[r][k] = D[(size_t)k * 64 + r * 8 + t];
    }
    __syncthreads();

    const float4* xr = reinterpret_cast<const float4*>(x + (size_t)row * 1024);
    __half* arow = Ap + (size_t)row * 1024;
    float acc[RNK];
#pragma unroll
    for (int r = 0; r < RNK; ++r) acc[r] = 0.f;
#pragma unroll
    for (int i = 0; i < 8; ++i) {
        int kq = lane + 32 * i;
        float4 v = xr[kq];
        int k = kq << 2;
        union { __half h[4]; uint2 u; } hp;
        hp.h[0] = __float2half(v.x);
        hp.h[1] = __float2half(v.y);
        hp.h[2] = __float2half(v.z);
        hp.h[3] = __float2half(v.w);
        *reinterpret_cast<uint2*>(arow + k) = hp.u;
#pragma unroll
        for (int r = 0; r < RNK; ++r) {
            float4 d = *reinterpret_cast<const float4*>(&Ds[r][k]);
            acc[r] += v.x * d.x + v.y * d.y + v.z * d.z + v.w * d.w;
        }
    }
#pragma unroll
    for (int r = 0; r < RNK; ++r) {
        float v = acc[r];
#pragma unroll
        for (int o = 16; o > 0; o >>= 1) v += __shfl_down_sync(0xffffffffu, v, o);
        if (lane == 0) P[(size_t)row * RNK + r] = v;
    }
}

// ---------------------------------------------------------------------------
// P[m,r] = sum_nb Pp[nb][m][r]
// ---------------------------------------------------------------------------
__global__ __launch_bounds__(256)
void reduceP_kernel(const float* __restrict__ Pp, float* __restrict__ P, int nb)
{
    int i = blockIdx.x * 256 + threadIdx.x;      // over M_ROWS*RNK = 65536
    float s = 0.f;
    for (int b = 0; b < nb; ++b) s += Pp[(size_t)b * (M_ROWS * RNK) + i];
    P[i] = s;
}

// ---------------------------------------------------------------------------
// W[K,N] fp32 -> B'[N,K] fp16 = W^T
// ---------------------------------------------------------------------------
__global__ __launch_bounds__(256)
void convertW_kernel(const float* __restrict__ W, __half* __restrict__ Bp,
                     int K, int N)
{
    __shared__ float t[32][33];
    int n0 = blockIdx.x * 32, k0 = blockIdx.y * 32;
    int tx = threadIdx.x & 31, ty = threadIdx.x >> 5;   // 32 x 8
#pragma unroll
    for (int i = 0; i < 4; ++i)
        t[ty + 8 * i][tx] = W[(size_t)(k0 + ty + 8 * i) * N + n0 + tx];
    __syncthreads();
#pragma unroll
    for (int i = 0; i < 4; ++i) {
        int nn = ty + 8 * i;
        Bp[(size_t)(n0 + nn) * K + k0 + tx] = __float2half(t[tx][nn]);
    }
}

// ---------------------------------------------------------------------------
// 3-stage pipelined fp16 mma.sync GEMM (champion geometry), 1 term per chunk:
//   acc = A*W   (fp32 accumulate)
// Fused epilogue + race-free next-layer LoRA-down partials.
// mode==1: fp16 output (stride N) + ReLU + fused P partials (Dn).
// mode==0: fp32 output (stride N), no ReLU, no P partials.
// ---------------------------------------------------------------------------
__global__ __launch_bounds__(256, 1)
void gemm_mma_kernel(const __half* __restrict__ Ap,
                     const __half* __restrict__ Bp,
                     const float* __restrict__ bias,
                     const float* __restrict__ P,
                     const float* __restrict__ U,
                     void* __restrict__ Cp,
                     const float* __restrict__ Dn,   // next-layer D or null
                     float* __restrict__ Pp,         // partial buffer or null
                     int K, int N, int mode)
{
    extern __shared__ char smem[];
    const uint32_t sbase = smem_u32(smem);
    const int tid  = threadIdx.x;
    const int wid  = tid >> 5;
    const int lane = tid & 31;
    const int mBase = blockIdx.y * BM;
    const int nBase = blockIdx.x * BN;
    const int task  = mBase >> 10;
    const int nChunks = K / BK;

    const int warp_m = (wid >> 2) * 64;   // 0 / 64
    const int warp_n = (wid & 3) * 32;    // 0 / 32 / 64 / 96

    // ---- producer addressing: 4 granules per tile per thread ---------------
    const __half* gA[4];
    const __half* gB[4];
    uint32_t sAB[4];
#pragma unroll
    for (int i = 0; i < 4; ++i) {
        int g = tid + (i << 8);           // 16B granule id 0..1023
        int r = g >> 3, q = g & 7;        // row 0..127, 16B col 0..7
        uint32_t off = (uint32_t)(r << 7) + (q << 4);
        sAB[i] = off ^ ((uint32_t)(r & 7) << 4);
        gA[i] = Ap + (size_t)(mBase + r) * (uint32_t)K + (q << 3);
        gB[i] = Bp + (size_t)(nBase + r) * (uint32_t)K + (q << 3);
    }

    float acc[4][4][4];
#pragma unroll
    for (int mi = 0; mi < 4; ++mi)
#pragma unroll
        for (int ni = 0; ni < 4; ++ni)
#pragma unroll
            for (int j = 0; j < 4; ++j) acc[mi][ni][j] = 0.f;

    // ---- prologue: fill STAGES-1 stages -----------------------------------
#pragma unroll
    for (int c = 0; c < STAGES - 1; ++c) {
        const uint32_t st = sbase + c * STAGE_BYTES;
        const int kc = c * BK;
#pragma unroll
        for (int i = 0; i < 4; ++i) {
            CP_ASYNC16(st + sAB[i],              gA[i] + kc);   // A
            CP_ASYNC16(st + TILE_BYTES + sAB[i], gB[i] + kc);   // W
        }
        CP_ASYNC_COMMIT();
    }

    // ---- ldmatrix addressing ----------------------------------------------
    uint32_t aRow[4], aXm[4];
    const uint32_t aCol = (uint32_t)(lane >> 4) << 4;
#pragma unroll
    for (int mi = 0; mi < 4; ++mi) {
        int r = warp_m + mi * 16 + (lane & 15);
        aRow[mi] = (uint32_t)r << 7;
        aXm[mi]  = (uint32_t)(r & 7) << 4;
    }
    // B paired x4: pair p covers ni = 2p, 2p+1
    uint32_t bRowP[2], bXmP[2];
    const uint32_t bCol = (uint32_t)((lane >> 3) & 1) << 4;
#pragma unroll
    for (int p = 0; p < 2; ++p) {
        int r = warp_n + (2 * p + ((lane >> 4) & 1)) * 8 + (lane & 7);
        bRowP[p] = (uint32_t)r << 7;
        bXmP[p]  = (uint32_t)(r & 7) << 4;
    }

    // ---- mainloop ----------------------------------------------------------
    int s = 0;
    for (int c = 0; c < nChunks; ++c) {
        CP_ASYNC_WAIT(STAGES - 2);
        __syncthreads();

        const uint32_t stA = sbase + s * STAGE_BYTES;
        const uint32_t stB = stA + TILE_BYTES;

#pragma unroll
        for (int kk = 0; kk < 4; ++kk) {
            const uint32_t kb = (uint32_t)kk << 5;
            uint32_t a[4][4], b[4][2];
#pragma unroll
            for (int mi = 0; mi < 4; ++mi) {
                uint32_t xo = (kb + aCol);
                LDMATRIX_X4(a[mi][0], a[mi][1], a[mi][2], a[mi][3],
                            stA + aRow[mi] + (xo ^ aXm[mi]));
            }
#pragma unroll
            for (int p = 0; p < 2; ++p) {
                uint32_t xo = (kb + bCol);
                LDMATRIX_X4(b[2*p][0], b[2*p][1], b[2*p+1][0], b[2*p+1][1],
                            stB + bRowP[p] + (xo ^ bXmP[p]));
            }
#pragma unroll
            for (int mi = 0; mi < 4; ++mi)
#pragma unroll
                for (int ni = 0; ni < 4; ++ni)
                    mma_fp16(acc[mi][ni], a[mi], b[ni]);
        }

        const int cn = c + STAGES - 1;
        if (cn < nChunks) {
            int sn = s + (STAGES - 1); if (sn >= STAGES) sn -= STAGES;
            const uint32_t st = sbase + sn * STAGE_BYTES;
            const int kc = cn * BK;
#pragma unroll
            for (int i = 0; i < 4; ++i) {
                CP_ASYNC16(st + sAB[i],              gA[i] + kc);
                CP_ASYNC16(st + TILE_BYTES + sAB[i], gB[i] + kc);
            }
        }
        CP_ASYNC_COMMIT();
        if (++s == STAGES) s = 0;
    }

    // ---- epilogue ----------------------------------------------------------
    CP_ASYNC_WAIT(0);
    __syncthreads();

    float* bias_s = reinterpret_cast<float*>(smem);                // [128]
    float* Us     = reinterpret_cast<float*>(smem + 1024);         // [8][128]
    float* Ps     = reinterpret_cast<float*>(smem + 1024 + 4096);  // [128][8]
    float* Dsn    = reinterpret_cast<float*>(smem + 1024 + 8192);  // [128][8]
    float* sPP    = reinterpret_cast<float*>(smem + 16384);        // [4][128][8]

    if (tid < BN) bias_s[tid] = bias[nBase + tid];
#pragma unroll
    for (int i = 0; i < 4; ++i) {
        int idx = tid + (i << 8);
        int r = idx >> 7, n = idx & 127;
        Us[idx] = U[((size_t)r * N + nBase + n) * T_TASKS + task];
    }
    {
        int row = tid >> 1, half = (tid & 1) << 2;
        float4 v = *reinterpret_cast<const float4*>(
            P + (size_t)(mBase + row) * RNK + half);
        *reinterpret_cast<float4*>(&Ps[row * RNK + half]) = v;
    }
    if (mode == 1) {
#pragma unroll
        for (int i = 0; i < 4; ++i) {
            int idx = tid + (i << 8);
            int n = idx >> 3, r = idx & 7;
            Dsn[idx] = Dn[(size_t)(nBase + n) * 64 + r * 8 + task];
        }
    }
    __syncthreads();

#pragma unroll
    for (int mi = 0; mi < 4; ++mi) {
#pragma unroll
        for (int half = 0; half < 2; ++half) {
            const int rloc = warp_m + mi * 16 + (lane >> 2) + half * 8;
            const int gm   = mBase + rloc;
            float pr[RNK];
            {
                float4 p0 = *reinterpret_cast<const float4*>(&Ps[rloc * RNK]);
                float4 p1 = *reinterpret_cast<const float4*>(&Ps[rloc * RNK + 4]);
                pr[0]=p0.x; pr[1]=p0.y; pr[2]=p0.z; pr[3]=p0.w;
                pr[4]=p1.x; pr[5]=p1.y; pr[6]=p1.z; pr[7]=p1.w;
            }
            float pp[RNK];
#pragma unroll
            for (int r = 0; r < RNK; ++r) pp[r] = 0.f;

#pragma unroll
            for (int ni = 0; ni < 4; ++ni) {
                const int nloc = warp_n + ni * 8 + ((lane & 3) << 1);
                float l0 = 0.f, l1 = 0.f;
#pragma unroll
                for (int q = 0; q < RNK; ++q) {
                    l0 += pr[q] * Us[(q << 7) + nloc];
                    l1 += pr[q] * Us[(q << 7) + nloc + 1];
                }
                float v0 = acc[mi][ni][half * 2 + 0] + bias_s[nloc]     + 2.f * l0;
                float v1 = acc[mi][ni][half * 2 + 1] + bias_s[nloc + 1] + 2.f * l1;
                if (mode == 1) {
                    v0 = fmaxf(v0, 0.f); v1 = fmaxf(v1, 0.f);
                    __half2 hv;
                    hv.x = __float2half(v0);
                    hv.y = __float2half(v1);
                    __half* orow = (__half*)Cp + (size_t)gm * N + nBase + nloc;
                    *reinterpret_cast<__half2*>(orow) = hv;
#pragma unroll
                    for (int r = 0; r < RNK; ++r)
                        pp[r] += v0 * Dsn[(nloc << 3) + r]
                               + v1 * Dsn[((nloc + 1) << 3) + r];
                } else {
                    float* crow = (float*)Cp + (size_t)gm * N + nBase + nloc;
                    *reinterpret_cast<float2*>(crow) = make_float2(v0, v1);
                }
            }

            if (mode == 1) {
                // reduce across the quad (4 lanes share rloc)
#pragma unroll
                for (int r = 0; r < RNK; ++r) {
                    pp[r] += __shfl_xor_sync(0xffffffffu, pp[r], 1);
                    pp[r] += __shfl_xor_sync(0xffffffffu, pp[r], 2);
                }
                // per-warp slot (wid&3 = n-group); disjoint rows per slot
                if ((lane & 3) == 0) {
                    float* dst = &sPP[(((wid & 3) << 7) + rloc) * RNK];
#pragma unroll
                    for (int r = 0; r < RNK; ++r) dst[r] = pp[r];
                }
            }
        }
    }

    if (mode == 1) {
        __syncthreads();
        // sum the 4 warp-n slots -> one deterministic partial per block
        for (int i = tid; i < BM * RNK; i += 256) {
            float sum = sPP[i] + sPP[1024 + i] + sPP[2048 + i] + sPP[3072 + i];
            Pp[(size_t)blockIdx.x * (M_ROWS * RNK) + (size_t)mBase * RNK + i] = sum;
        }
    }
}

// ---------------------------------------------------------------------------
// Host launcher
// ---------------------------------------------------------------------------
extern "C" void kernel_launch(void* const* d_in, const int* in_sizes, int n_in,
                              void* d_out, int out_size)
{
    const float* x  = (const float*)d_in[0];
    const float* k0 = (const float*)d_in[1];
    const float* b0 = (const float*)d_in[2];
    const float* d0 = (const float*)d_in[3];
    const float* u0 = (const float*)d_in[4];
    const float* k1 = (const float*)d_in[5];
    const float* b1 = (const float*)d_in[6];
    const float* d1 = (const float*)d_in[7];
    const float* u1 = (const float*)d_in[8];
    const float* k2 = (const float*)d_in[9];
    const float* b2 = (const float*)d_in[10];
    const float* d2 = (const float*)d_in[11];
    const float* u2 = (const float*)d_in[12];
    float* out = (float*)d_out;

    __half *a0, *a1, *bS;
    float *p, *pp;
    cudaGetSymbolAddress((void**)&a0, g_A0);
    cudaGetSymbolAddress((void**)&a1, g_A1);
    cudaGetSymbolAddress((void**)&bS, g_B);
    cudaGetSymbolAddress((void**)&p,  g_p);
    cudaGetSymbolAddress((void**)&pp, g_pp);

    cudaFuncSetAttribute(gemm_mma_kernel,
                         cudaFuncAttributeMaxDynamicSharedMemorySize, SMEM_BYTES);

    // layer-0 prep: x -> A0 fp16 + P0, single pass over x
    prep0_kernel<<<M_ROWS / 8, 256>>>(x, d0, a0, p);

    // layer 0: A0[.,1024] -> A1[.,2048] fp16+ReLU, fused P' partials (d1)
    convertW_kernel<<<dim3(2048 / 32, 1024 / 32), 256>>>(k0, bS, 1024, 2048);
    gemm_mma_kernel<<<dim3(2048 / BN, M_ROWS / BM), 256, SMEM_BYTES>>>(
        a0, bS, b0, p, u0, a1, d1, pp, 1024, 2048, 1);
    reduceP_kernel<<<(M_ROWS * RNK) / 256, 256>>>(pp, p, 2048 / BN);

    // layer 1: A1[.,2048] -> A0[.,2048] fp16+ReLU, fused P' partials (d2)
    convertW_kernel<<<dim3(2048 / 32, 2048 / 32), 256>>>(k1, bS, 2048, 2048);
    gemm_mma_kernel<<<dim3(2048 / BN, M_ROWS / BM), 256, SMEM_BYTES>>>(
        a1, bS, b1, p, u1, a0, d2, pp, 2048, 2048, 1);
    reduceP_kernel<<<(M_ROWS * RNK) / 256, 256>>>(pp, p, 2048 / BN);

    // layer 2: A0[.,2048] -> out fp32 [.,1024], no ReLU
    convertW_kernel<<<dim3(1024 / 32, 2048 / 32), 256>>>(k2, bS, 2048, 1024);
    gemm_mma_kernel<<<dim3(1024 / BN, M_ROWS / BM), 256, SMEM_BYTES>>>(
        a0, bS, b2, p, u2, out, nullptr, nullptr, 2048, 1024, 0);
}

// round 14
// speedup vs baseline: 2.4225x; 1.0190x over previous
#include <cuda_runtime.h>
#include <cuda_fp16.h>
#include <cstdint>

// ---------------------------------------------------------------------------
// LoRA multi-task MLP via mma.sync fp16 (plain sm_100 target).
// Round 14: R13 champion (1-term fp16 GEMM, BM=BN=128, BK=64, 3 stages,
// 8 warps, 64x32 warp tile) + 2 CTAs/SM (96KB smem/CTA, regs capped 128)
// + prefetch-before-compute mainloop ordering.
// ---------------------------------------------------------------------------

#define T_TASKS 8
#define RNK 8
#define M_ROWS 8192

#define BM 128
#define BN 128
#define BK 64                          // K elements per chunk (128 B fp16 rows)
#define STAGES 3
#define TILE_BYTES (128 * 128)         // 16 KB per operand tile
#define STAGE_BYTES (2 * TILE_BYTES)   // A | W = 32 KB
#define SMEM_BYTES (STAGES * STAGE_BYTES)   // 96 KB -> 2 CTAs/SM

// ---- scratch (device globals; no allocation allowed) ----------------------
__device__ __half g_A0[(size_t)M_ROWS * 2048];   // fp16 activations, 32 MB
__device__ __half g_A1[(size_t)M_ROWS * 2048];   // fp16 activations, 32 MB
__device__ __half g_B [(size_t)2048   * 2048];   // W^T fp16, 8 MB
__device__ float g_p [M_ROWS * RNK];
__device__ float g_pp[16 * M_ROWS * RNK];        // per-n-block partials

// ---------------------------------------------------------------------------
__device__ __forceinline__ uint32_t smem_u32(const void* p) {
    uint32_t a;
    asm("{ .reg .u64 t; cvta.to.shared.u64 t, %1; cvt.u32.u64 %0, t; }"
        : "=r"(a) : "l"(p));
    return a;
}

#define CP_ASYNC16(smem, gptr) \
    asm volatile("cp.async.cg.shared.global [%0], [%1], 16;" \
                 :: "r"(smem), "l"(gptr) : "memory")
#define CP_ASYNC_COMMIT() asm volatile("cp.async.commit_group;" ::: "memory")
#define CP_ASYNC_WAIT(n)  asm volatile("cp.async.wait_group %0;" :: "n"(n) : "memory")

#define LDMATRIX_X4(r0,r1,r2,r3,addr) \
    asm volatile("ldmatrix.sync.aligned.m8n8.x4.shared.b16 {%0,%1,%2,%3}, [%4];" \
        : "=r"(r0),"=r"(r1),"=r"(r2),"=r"(r3) : "r"(addr))

__device__ __forceinline__ void mma_fp16(float* c, const uint32_t* a,
                                         const uint32_t* b) {
    asm volatile(
        "mma.sync.aligned.m16n8k16.row.col.f32.f16.f16.f32 "
        "{%0,%1,%2,%3}, {%4,%5,%6,%7}, {%8,%9}, {%0,%1,%2,%3};"
        : "+f"(c[0]), "+f"(c[1]), "+f"(c[2]), "+f"(c[3])
        : "r"(a[0]), "r"(a[1]), "r"(a[2]), "r"(a[3]), "r"(b[0]), "r"(b[1]));
}

// ---------------------------------------------------------------------------
// Fused layer-0 prep: x fp32 -> A0 fp16 AND P0[m,r] = x·D0[:,r,t].
// ---------------------------------------------------------------------------
__global__ __launch_bounds__(256)
void prep0_kernel(const float* __restrict__ x, const float* __restrict__ D,
                  __half* __restrict__ Ap, float* __restrict__ P)
{
    __shared__ float Ds[RNK][1024];
    const int tid  = threadIdx.x;
    const int wid  = tid >> 5;
    const int lane = tid & 31;
    const int row  = blockIdx.x * 8 + wid;
    const int t    = (blockIdx.x * 8) >> 10;

    for (int idx = tid; idx < 1024 * RNK; idx += 256) {
        int k = idx >> 3, r = idx & 7;
        Ds[r][k] = D[(size_t)k * 64 + r * 8 + t];
    }
    __syncthreads();

    const float4* xr = reinterpret_cast<const float4*>(x + (size_t)row * 1024);
    __half* arow = Ap + (size_t)row * 1024;
    float acc[RNK];
#pragma unroll
    for (int r = 0; r < RNK; ++r) acc[r] = 0.f;
#pragma unroll
    for (int i = 0; i < 8; ++i) {
        int kq = lane + 32 * i;
        float4 v = xr[kq];
        int k = kq << 2;
        union { __half h[4]; uint2 u; } hp;
        hp.h[0] = __float2half(v.x);
        hp.h[1] = __float2half(v.y);
        hp.h[2] = __float2half(v.z);
        hp.h[3] = __float2half(v.w);
        *reinterpret_cast<uint2*>(arow + k) = hp.u;
#pragma unroll
        for (int r = 0; r < RNK; ++r) {
            float4 d = *reinterpret_cast<const float4*>(&Ds[r][k]);
            acc[r] += v.x * d.x + v.y * d.y + v.z * d.z + v.w * d.w;
        }
    }
#pragma unroll
    for (int r = 0; r < RNK; ++r) {
        float v = acc[r];
#pragma unroll
        for (int o = 16; o > 0; o >>= 1) v += __shfl_down_sync(0xffffffffu, v, o);
        if (lane == 0) P[(size_t)row * RNK + r] = v;
    }
}

// ---------------------------------------------------------------------------
// P[m,r] = sum_nb Pp[nb][m][r]
// ---------------------------------------------------------------------------
__global__ __launch_bounds__(256)
void reduceP_kernel(const float* __restrict__ Pp, float* __restrict__ P, int nb)
{
    int i = blockIdx.x * 256 + threadIdx.x;      // over M_ROWS*RNK = 65536
    float s = 0.f;
    for (int b = 0; b < nb; ++b) s += Pp[(size_t)b * (M_ROWS * RNK) + i];
    P[i] = s;
}

// ---------------------------------------------------------------------------
// W[K,N] fp32 -> B'[N,K] fp16 = W^T
// ---------------------------------------------------------------------------
__global__ __launch_bounds__(256)
void convertW_kernel(const float* __restrict__ W, __half* __restrict__ Bp,
                     int K, int N)
{
    __shared__ float t[32][33];
    int n0 = blockIdx.x * 32, k0 = blockIdx.y * 32;
    int tx = threadIdx.x & 31, ty = threadIdx.x >> 5;   // 32 x 8
#pragma unroll
    for (int i = 0; i < 4; ++i)
        t[ty + 8 * i][tx] = W[(size_t)(k0 + ty + 8 * i) * N + n0 + tx];
    __syncthreads();
#pragma unroll
    for (int i = 0; i < 4; ++i) {
        int nn = ty + 8 * i;
        Bp[(size_t)(n0 + nn) * K + k0 + tx] = __float2half(t[tx][nn]);
    }
}

// ---------------------------------------------------------------------------
// 3-stage pipelined fp16 mma.sync GEMM, 2 CTAs/SM, prefetch-before-compute.
//   acc = A*W   (fp32 accumulate)
// Fused epilogue + race-free next-layer LoRA-down partials.
// mode==1: fp16 output (stride N) + ReLU + fused P partials (Dn).
// mode==0: fp32 output (stride N), no ReLU, no P partials.
// ---------------------------------------------------------------------------
__global__ __launch_bounds__(256, 2)
void gemm_mma_kernel(const __half* __restrict__ Ap,
                     const __half* __restrict__ Bp,
                     const float* __restrict__ bias,
                     const float* __restrict__ P,
                     const float* __restrict__ U,
                     void* __restrict__ Cp,
                     const float* __restrict__ Dn,   // next-layer D or null
                     float* __restrict__ Pp,         // partial buffer or null
                     int K, int N, int mode)
{
    extern __shared__ char smem[];
    const uint32_t sbase = smem_u32(smem);
    const int tid  = threadIdx.x;
    const int wid  = tid >> 5;
    const int lane = tid & 31;
    const int mBase = blockIdx.y * BM;
    const int nBase = blockIdx.x * BN;
    const int task  = mBase >> 10;
    const int nChunks = K / BK;

    const int warp_m = (wid >> 2) * 64;   // 0 / 64
    const int warp_n = (wid & 3) * 32;    // 0 / 32 / 64 / 96

    // ---- producer addressing: 4 granules per tile per thread ---------------
    const __half* gA[4];
    const __half* gB[4];
    uint32_t sAB[4];
#pragma unroll
    for (int i = 0; i < 4; ++i) {
        int g = tid + (i << 8);           // 16B granule id 0..1023
        int r = g >> 3, q = g & 7;        // row 0..127, 16B col 0..7
        uint32_t off = (uint32_t)(r << 7) + (q << 4);
        sAB[i] = off ^ ((uint32_t)(r & 7) << 4);
        gA[i] = Ap + (size_t)(mBase + r) * (uint32_t)K + (q << 3);
        gB[i] = Bp + (size_t)(nBase + r) * (uint32_t)K + (q << 3);
    }

    float acc[4][4][4];
#pragma unroll
    for (int mi = 0; mi < 4; ++mi)
#pragma unroll
        for (int ni = 0; ni < 4; ++ni)
#pragma unroll
            for (int j = 0; j < 4; ++j) acc[mi][ni][j] = 0.f;

    // ---- prologue: fill STAGES-1 stages -----------------------------------
#pragma unroll
    for (int c = 0; c < STAGES - 1; ++c) {
        const uint32_t st = sbase + c * STAGE_BYTES;
        const int kc = c * BK;
#pragma unroll
        for (int i = 0; i < 4; ++i) {
            CP_ASYNC16(st + sAB[i],              gA[i] + kc);   // A
            CP_ASYNC16(st + TILE_BYTES + sAB[i], gB[i] + kc);   // W
        }
        CP_ASYNC_COMMIT();
    }

    // ---- ldmatrix addressing ----------------------------------------------
    uint32_t aRow[4], aXm[4];
    const uint32_t aCol = (uint32_t)(lane >> 4) << 4;
#pragma unroll
    for (int mi = 0; mi < 4; ++mi) {
        int r = warp_m + mi * 16 + (lane & 15);
        aRow[mi] = (uint32_t)r << 7;
        aXm[mi]  = (uint32_t)(r & 7) << 4;
    }
    // B paired x4: pair p covers ni = 2p, 2p+1
    uint32_t bRowP[2], bXmP[2];
    const uint32_t bCol = (uint32_t)((lane >> 3) & 1) << 4;
#pragma unroll
    for (int p = 0; p < 2; ++p) {
        int r = warp_n + (2 * p + ((lane >> 4) & 1)) * 8 + (lane & 7);
        bRowP[p] = (uint32_t)r << 7;
        bXmP[p]  = (uint32_t)(r & 7) << 4;
    }

    // ---- mainloop: wait -> sync -> prefetch -> compute ----------------------
    int s = 0;
    for (int c = 0; c < nChunks; ++c) {
        CP_ASYNC_WAIT(STAGES - 2);
        __syncthreads();

        // prefetch chunk c+STAGES-1 into the stage freed by chunk c-1
        const int cn = c + STAGES - 1;
        if (cn < nChunks) {
            int sn = s + (STAGES - 1); if (sn >= STAGES) sn -= STAGES;
            const uint32_t st = sbase + sn * STAGE_BYTES;
            const int kc = cn * BK;
#pragma unroll
            for (int i = 0; i < 4; ++i) {
                CP_ASYNC16(st + sAB[i],              gA[i] + kc);
                CP_ASYNC16(st + TILE_BYTES + sAB[i], gB[i] + kc);
            }
        }
        CP_ASYNC_COMMIT();

        const uint32_t stA = sbase + s * STAGE_BYTES;
        const uint32_t stB = stA + TILE_BYTES;

#pragma unroll
        for (int kk = 0; kk < 4; ++kk) {
            const uint32_t kb = (uint32_t)kk << 5;
            uint32_t a[4][4], b[4][2];
#pragma unroll
            for (int mi = 0; mi < 4; ++mi) {
                uint32_t xo = (kb + aCol);
                LDMATRIX_X4(a[mi][0], a[mi][1], a[mi][2], a[mi][3],
                            stA + aRow[mi] + (xo ^ aXm[mi]));
            }
#pragma unroll
            for (int p = 0; p < 2; ++p) {
                uint32_t xo = (kb + bCol);
                LDMATRIX_X4(b[2*p][0], b[2*p][1], b[2*p+1][0], b[2*p+1][1],
                            stB + bRowP[p] + (xo ^ bXmP[p]));
            }
#pragma unroll
            for (int mi = 0; mi < 4; ++mi)
#pragma unroll
                for (int ni = 0; ni < 4; ++ni)
                    mma_fp16(acc[mi][ni], a[mi], b[ni]);
        }

        if (++s == STAGES) s = 0;
    }

    // ---- epilogue ----------------------------------------------------------
    CP_ASYNC_WAIT(0);
    __syncthreads();

    float* bias_s = reinterpret_cast<float*>(smem);                // [128]
    float* Us     = reinterpret_cast<float*>(smem + 1024);         // [8][128]
    float* Ps     = reinterpret_cast<float*>(smem + 1024 + 4096);  // [128][8]
    float* Dsn    = reinterpret_cast<float*>(smem + 1024 + 8192);  // [128][8]
    float* sPP    = reinterpret_cast<float*>(smem + 16384);        // [4][128][8]

    if (tid < BN) bias_s[tid] = bias[nBase + tid];
#pragma unroll
    for (int i = 0; i < 4; ++i) {
        int idx = tid + (i << 8);
        int r = idx >> 7, n = idx & 127;
        Us[idx] = U[((size_t)r * N + nBase + n) * T_TASKS + task];
    }
    {
        int row = tid >> 1, half = (tid & 1) << 2;
        float4 v = *reinterpret_cast<const float4*>(
            P + (size_t)(mBase + row) * RNK + half);
        *reinterpret_cast<float4*>(&Ps[row * RNK + half]) = v;
    }
    if (mode == 1) {
#pragma unroll
        for (int i = 0; i < 4; ++i) {
            int idx = tid + (i << 8);
            int n = idx >> 3, r = idx & 7;
            Dsn[idx] = Dn[(size_t)(nBase + n) * 64 + r * 8 + task];
        }
    }
    __syncthreads();

#pragma unroll
    for (int mi = 0; mi < 4; ++mi) {
#pragma unroll
        for (int half = 0; half < 2; ++half) {
            const int rloc = warp_m + mi * 16 + (lane >> 2) + half * 8;
            const int gm   = mBase + rloc;
            float pr[RNK];
            {
                float4 p0 = *reinterpret_cast<const float4*>(&Ps[rloc * RNK]);
                float4 p1 = *reinterpret_cast<const float4*>(&Ps[rloc * RNK + 4]);
                pr[0]=p0.x; pr[1]=p0.y; pr[2]=p0.z; pr[3]=p0.w;
                pr[4]=p1.x; pr[5]=p1.y; pr[6]=p1.z; pr[7]=p1.w;
            }
            float pp[RNK];
#pragma unroll
            for (int r = 0; r < RNK; ++r) pp[r] = 0.f;

#pragma unroll
            for (int ni = 0; ni < 4; ++ni) {
                const int nloc = warp_n + ni * 8 + ((lane & 3) << 1);
                float l0 = 0.f, l1 = 0.f;
#pragma unroll
                for (int q = 0; q < RNK; ++q) {
                    l0 += pr[q] * Us[(q << 7) + nloc];
                    l1 += pr[q] * Us[(q << 7) + nloc + 1];
                }
                float v0 = acc[mi][ni][half * 2 + 0] + bias_s[nloc]     + 2.f * l0;
                float v1 = acc[mi][ni][half * 2 + 1] + bias_s[nloc + 1] + 2.f * l1;
                if (mode == 1) {
                    v0 = fmaxf(v0, 0.f); v1 = fmaxf(v1, 0.f);
                    __half2 hv;
                    hv.x = __float2half(v0);
                    hv.y = __float2half(v1);
                    __half* orow = (__half*)Cp + (size_t)gm * N + nBase + nloc;
                    *reinterpret_cast<__half2*>(orow) = hv;
#pragma unroll
                    for (int r = 0; r < RNK; ++r)
                        pp[r] += v0 * Dsn[(nloc << 3) + r]
                               + v1 * Dsn[((nloc + 1) << 3) + r];
                } else {
                    float* crow = (float*)Cp + (size_t)gm * N + nBase + nloc;
                    *reinterpret_cast<float2*>(crow) = make_float2(v0, v1);
                }
            }

            if (mode == 1) {
                // reduce across the quad (4 lanes share rloc)
#pragma unroll
                for (int r = 0; r < RNK; ++r) {
                    pp[r] += __shfl_xor_sync(0xffffffffu, pp[r], 1);
                    pp[r] += __shfl_xor_sync(0xffffffffu, pp[r], 2);
                }
                // per-warp slot (wid&3 = n-group); disjoint rows per slot
                if ((lane & 3) == 0) {
                    float* dst = &sPP[(((wid & 3) << 7) + rloc) * RNK];
#pragma unroll
                    for (int r = 0; r < RNK; ++r) dst[r] = pp[r];
                }
            }
        }
    }

    if (mode == 1) {
        __syncthreads();
        // sum the 4 warp-n slots -> one deterministic partial per block
        for (int i = tid; i < BM * RNK; i += 256) {
            float sum = sPP[i] + sPP[1024 + i] + sPP[2048 + i] + sPP[3072 + i];
            Pp[(size_t)blockIdx.x * (M_ROWS * RNK) + (size_t)mBase * RNK + i] = sum;
        }
    }
}

// ---------------------------------------------------------------------------
// Host launcher
// ---------------------------------------------------------------------------
extern "C" void kernel_launch(void* const* d_in, const int* in_sizes, int n_in,
                              void* d_out, int out_size)
{
    const float* x  = (const float*)d_in[0];
    const float* k0 = (const float*)d_in[1];
    const float* b0 = (const float*)d_in[2];
    const float* d0 = (const float*)d_in[3];
    const float* u0 = (const float*)d_in[4];
    const float* k1 = (const float*)d_in[5];
    const float* b1 = (const float*)d_in[6];
    const float* d1 = (const float*)d_in[7];
    const float* u1 = (const float*)d_in[8];
    const float* k2 = (const float*)d_in[9];
    const float* b2 = (const float*)d_in[10];
    const float* d2 = (const float*)d_in[11];
    const float* u2 = (const float*)d_in[12];
    float* out = (float*)d_out;

    __half *a0, *a1, *bS;
    float *p, *pp;
    cudaGetSymbolAddress((void**)&a0, g_A0);
    cudaGetSymbolAddress((void**)&a1, g_A1);
    cudaGetSymbolAddress((void**)&bS, g_B);
    cudaGetSymbolAddress((void**)&p,  g_p);
    cudaGetSymbolAddress((void**)&pp, g_pp);

    cudaFuncSetAttribute(gemm_mma_kernel,
                         cudaFuncAttributeMaxDynamicSharedMemorySize, SMEM_BYTES);

    // layer-0 prep: x -> A0 fp16 + P0, single pass over x
    prep0_kernel<<<M_ROWS / 8, 256>>>(x, d0, a0, p);

    // layer 0: A0[.,1024] -> A1[.,2048] fp16+ReLU, fused P' partials (d1)
    convertW_kernel<<<dim3(2048 / 32, 1024 / 32), 256>>>(k0, bS, 1024, 2048);
    gemm_mma_kernel<<<dim3(2048 / BN, M_ROWS / BM), 256, SMEM_BYTES>>>(
        a0, bS, b0, p, u0, a1, d1, pp, 1024, 2048, 1);
    reduceP_kernel<<<(M_ROWS * RNK) / 256, 256>>>(pp, p, 2048 / BN);

    // layer 1: A1[.,2048] -> A0[.,2048] fp16+ReLU, fused P' partials (d2)
    convertW_kernel<<<dim3(2048 / 32, 2048 / 32), 256>>>(k1, bS, 2048, 2048);
    gemm_mma_kernel<<<dim3(2048 / BN, M_ROWS / BM), 256, SMEM_BYTES>>>(
        a1, bS, b1, p, u1, a0, d2, pp, 2048, 2048, 1);
    reduceP_kernel<<<(M_ROWS * RNK) / 256, 256>>>(pp, p, 2048 / BN);

    // layer 2: A0[.,2048] -> out fp32 [.,1024], no ReLU
    convertW_kernel<<<dim3(1024 / 32, 2048 / 32), 256>>>(k2, bS, 2048, 1024);
    gemm_mma_kernel<<<dim3(1024 / BN, M_ROWS / BM), 256, SMEM_BYTES>>>(
        a0, bS, b2, p, u2, out, nullptr, nullptr, 2048, 1024, 0);
}